// round 7
// baseline (speedup 1.0000x reference)
#include <cuda_runtime.h>
#include <cstdint>

#define B_DIM 2048
#define S_DIM 32768
#define G_DIM 4096
#define E_DIM 1024

// ---------------- scratch (static device globals; no allocation) ----------------
__device__ float    g_xpt[(size_t)S_DIM * B_DIM];  // permuted+transformed transpose (S,B)
__device__ float    g_zt [(size_t)G_DIM * B_DIM];  // relu(finalized y), tf32-rounded, (G,B)
__device__ unsigned g_wt [(size_t)E_DIM * G_DIM];  // W pre-rounded to tf32 bits
__device__ int      g_dest[S_DIM];
__device__ float    g_coef[S_DIM];
__device__ int      g_isor[S_DIM];
__device__ int      g_segstart[G_DIM + 1];

__device__ __forceinline__ unsigned cvt_tf32(float f) {
    unsigned r;
    asm("cvt.rna.tf32.f32 %0, %1;" : "=r"(r) : "f"(f));
    return r;
}

// ---------------- prep ----------------
__global__ void prep_kernel(const float* __restrict__ w_elem,
                            const int* __restrict__ perm,
                            const int* __restrict__ seg,
                            const int* __restrict__ agg) {
    int s = blockIdx.x * blockDim.x + threadIdx.x;
    if (s >= S_DIM) return;
    int c = perm[s];
    int g = seg[s];
    int t = agg[g];
    g_dest[c] = s;
    g_coef[c] = (t == 2) ? w_elem[s] : 1.0f;
    g_isor[c] = (t == 1) ? 1 : 0;
    if (s == 0 || seg[s - 1] != g) g_segstart[g] = s;
    if (s == S_DIM - 1) g_segstart[G_DIM] = S_DIM;
}

// Pre-round W to tf32 (GEMM then feeds raw bits: zero bias, zero cvt in hot loop).
__global__ void wcvt_kernel(const float* __restrict__ W) {
    size_t i = ((size_t)blockIdx.x * 256 + threadIdx.x) * 4;
    float4 v = *(const float4*)&W[i];
    uint4 r;
    r.x = cvt_tf32(v.x); r.y = cvt_tf32(v.y);
    r.z = cvt_tf32(v.z); r.w = cvt_tf32(v.w);
    *(uint4*)&g_wt[i] = r;
}

// ---------------- phase 1: tiled transpose + transform ----------------
// Load: coalesced along c. Store: one s-row = 8 lanes x float4 = 128B, STG.128.
__global__ void transpose_kernel(const float* __restrict__ x) {
    __shared__ float tile[32][33];           // tile[b_local][c_local]
    int c0 = blockIdx.x * 32;
    int b0 = blockIdx.y * 32;
    int tx = threadIdx.x, ty = threadIdx.y;
    #pragma unroll
    for (int j = 0; j < 4; j++) {
        int b = b0 + ty + j * 8;
        tile[ty + j * 8][tx] = x[(size_t)b * S_DIM + c0 + tx];
    }
    __syncthreads();

    int tid = ty * 32 + tx;
    int c_row = tid / 8;                     // 0..31 (local c)
    int th    = tid % 8;                     // 0..7  (b float4 slot)
    int c = c0 + c_row;
    int s = g_dest[c];
    float coef = g_coef[c];
    int isor = g_isor[c];
    float4 v;
    // bank = (th*4 + i + c_row) % 32 -> conflict-free per i
    v.x = tile[th * 4 + 0][c_row];
    v.y = tile[th * 4 + 1][c_row];
    v.z = tile[th * 4 + 2][c_row];
    v.w = tile[th * 4 + 3][c_row];
    if (isor) {
        v.x = v.x != 0.0f ? 1.0f : 0.0f;
        v.y = v.y != 0.0f ? 1.0f : 0.0f;
        v.z = v.z != 0.0f ? 1.0f : 0.0f;
        v.w = v.w != 0.0f ? 1.0f : 0.0f;
    } else {
        v.x *= coef; v.y *= coef; v.z *= coef; v.w *= coef;
    }
    *(float4*)&g_xpt[(size_t)s * B_DIM + b0 + th * 4] = v;
}

// ---------------- phase 2: segmented sum + finalize + relu + tf32 round -------
__global__ void segreduce_kernel(const int* __restrict__ agg) {
    int b4 = blockIdx.x * 256 + threadIdx.x;
    int g = blockIdx.y;
    int s0 = g_segstart[g];
    int s1 = g_segstart[g + 1];
    float4 acc = make_float4(0.f, 0.f, 0.f, 0.f);
    for (int s = s0; s < s1; s++) {
        float4 v = *(const float4*)&g_xpt[(size_t)s * B_DIM + b4 * 4];
        acc.x += v.x; acc.y += v.y; acc.z += v.z; acc.w += v.w;
    }
    int t = agg[g];
    if (t == 1) {
        acc.x = acc.x > 0.f ? 1.f : 0.f;
        acc.y = acc.y > 0.f ? 1.f : 0.f;
        acc.z = acc.z > 0.f ? 1.f : 0.f;
        acc.w = acc.w > 0.f ? 1.f : 0.f;
    }
    acc.x = __uint_as_float(cvt_tf32(fmaxf(acc.x, 0.f)));
    acc.y = __uint_as_float(cvt_tf32(fmaxf(acc.y, 0.f)));
    acc.z = __uint_as_float(cvt_tf32(fmaxf(acc.z, 0.f)));
    acc.w = __uint_as_float(cvt_tf32(fmaxf(acc.w, 0.f)));
    *(float4*)&g_zt[(size_t)g * B_DIM + b4 * 4] = acc;
}

// ---------------- phase 3: tf32 mma.sync GEMM, cp.async double-buffered -------
// outT[e][b] = sum_g W[e][g] * zt[g][b];  A = g_wt (row-major e,g), B = g_zt (g,b)
// Tile 128(e) x 64(b) x 32(g); 8 warps (warp = 32e x 32b); 2 CTAs/SM; 48KB smem.
#define TILE_M 128
#define TILE_N 64
#define TILE_K 32

__device__ __forceinline__ void cp16(void* smem, const void* gmem) {
    unsigned saddr = (unsigned)__cvta_generic_to_shared(smem);
    asm volatile("cp.async.cg.shared.global [%0], [%1], 16;" :: "r"(saddr), "l"(gmem));
}

__global__ __launch_bounds__(256, 2) void gemm_kernel(float* __restrict__ out) {
    // XOR-swizzled, no padding: exactly 48KB for 2 stages.
    __shared__ unsigned As[2][TILE_M][TILE_K];  // [m=e][k], phys k' = k ^ (4*(m%8))
    __shared__ unsigned Bs[2][TILE_K][TILE_N];  // [k][n=b], phys n' = n ^ (8*(k%8))

    int tid = threadIdx.x;
    int warp = tid / 32;
    int lane = tid % 32;
    int e0 = blockIdx.x * TILE_M;
    int b0 = blockIdx.y * TILE_N;
    int wm = (warp % 4) * 32;
    int wn = (warp / 4) * 32;

    // Global->smem load mapping (float4 per cp.async)
    int a_row = tid / 8;                              // +32 per pass, 4 passes
    int a_k4  = tid % 8;
    int b_k   = tid / 16;                             // +16 per pass, 2 passes
    int b_n4  = tid % 16;
    int a_scol = (a_k4 * 4) ^ ((a_row % 8) * 4);      // swizzled store col (A)
    int b_scol = (b_n4 * 4) ^ ((b_k % 8) * 8);        // swizzled store col (B)

    const unsigned* Wp = g_wt;
    const unsigned* Zp = (const unsigned*)g_zt;

    float acc[2][4][4];
    #pragma unroll
    for (int i = 0; i < 2; i++)
        #pragma unroll
        for (int j = 0; j < 4; j++)
            #pragma unroll
            for (int r = 0; r < 4; r++) acc[i][j][r] = 0.f;

    int row = lane / 4;   // 0..7
    int col = lane % 4;   // 0..3

    // Prefetch tile 0 into buffer 0
    #pragma unroll
    for (int p = 0; p < 4; p++)
        cp16(&As[0][a_row + p * 32][a_scol],
             &Wp[(size_t)(e0 + a_row + p * 32) * G_DIM + a_k4 * 4]);
    #pragma unroll
    for (int p = 0; p < 2; p++)
        cp16(&Bs[0][b_k + p * 16][b_scol],
             &Zp[(size_t)(b_k + p * 16) * B_DIM + b0 + b_n4 * 4]);
    asm volatile("cp.async.commit_group;");

    const int T = G_DIM / TILE_K;   // 128
    for (int t = 0; t < T; t++) {
        int cur = t & 1;
        if (t + 1 < T) {
            int nxt = (t + 1) & 1;
            int g0 = (t + 1) * TILE_K;
            #pragma unroll
            for (int p = 0; p < 4; p++)
                cp16(&As[nxt][a_row + p * 32][a_scol],
                     &Wp[(size_t)(e0 + a_row + p * 32) * G_DIM + g0 + a_k4 * 4]);
            #pragma unroll
            for (int p = 0; p < 2; p++)
                cp16(&Bs[nxt][b_k + p * 16][b_scol],
                     &Zp[(size_t)(g0 + b_k + p * 16) * B_DIM + b0 + b_n4 * 4]);
            asm volatile("cp.async.commit_group;");
            asm volatile("cp.async.wait_group 1;");
        } else {
            asm volatile("cp.async.wait_group 0;");
        }
        __syncthreads();

        #pragma unroll
        for (int s = 0; s < 4; s++) {
            int ac0 = (s * 8 + col) ^ (4 * row);          // A phys col (k-lo)
            int ac1 = ac0 ^ 4;                            // k-hi (+4)
            unsigned af[2][4], bf[4][2];
            #pragma unroll
            for (int i = 0; i < 2; i++) {
                int m = wm + i * 16 + row;
                af[i][0] = As[cur][m    ][ac0];
                af[i][1] = As[cur][m + 8][ac0];
                af[i][2] = As[cur][m    ][ac1];
                af[i][3] = As[cur][m + 8][ac1];
            }
            int kr0 = s * 8 + col;                        // B k rows
            int swz = 8 * col;
            #pragma unroll
            for (int j = 0; j < 4; j++) {
                int n = wn + j * 8 + row;
                bf[j][0] = Bs[cur][kr0    ][n ^ swz];
                bf[j][1] = Bs[cur][kr0 + 4][n ^ swz ^ 32];
            }
            #pragma unroll
            for (int i = 0; i < 2; i++)
                #pragma unroll
                for (int j = 0; j < 4; j++) {
                    asm volatile(
                        "mma.sync.aligned.m16n8k8.row.col.f32.tf32.tf32.f32 "
                        "{%0,%1,%2,%3}, {%4,%5,%6,%7}, {%8,%9}, {%0,%1,%2,%3};"
                        : "+f"(acc[i][j][0]), "+f"(acc[i][j][1]),
                          "+f"(acc[i][j][2]), "+f"(acc[i][j][3])
                        : "r"(af[i][0]), "r"(af[i][1]), "r"(af[i][2]), "r"(af[i][3]),
                          "r"(bf[j][0]), "r"(bf[j][1]));
                }
        }
        __syncthreads();
    }

    // Epilogue: out[b][e]; c-frag: c0:(m=row,n=2col) c1:(row,2col+1) c2/c3: m=row+8
    #pragma unroll
    for (int i = 0; i < 2; i++) {
        int e_lo = e0 + wm + i * 16 + row;
        #pragma unroll
        for (int j = 0; j < 4; j++) {
            int b_base = b0 + wn + j * 8 + col * 2;
            out[(size_t)(b_base    ) * E_DIM + e_lo    ] = acc[i][j][0];
            out[(size_t)(b_base + 1) * E_DIM + e_lo    ] = acc[i][j][1];
            out[(size_t)(b_base    ) * E_DIM + e_lo + 8] = acc[i][j][2];
            out[(size_t)(b_base + 1) * E_DIM + e_lo + 8] = acc[i][j][3];
        }
    }
}

// ---------------- launch ----------------
extern "C" void kernel_launch(void* const* d_in, const int* in_sizes, int n_in,
                              void* d_out, int out_size) {
    const float* x      = (const float*)d_in[0];
    const float* W      = (const float*)d_in[1];
    const float* w_elem = (const float*)d_in[2];
    const int*   perm   = (const int*)d_in[3];
    const int*   seg    = (const int*)d_in[4];
    const int*   agg    = (const int*)d_in[5];
    float* out = (float*)d_out;

    prep_kernel<<<S_DIM / 256, 256>>>(w_elem, perm, seg, agg);
    wcvt_kernel<<<(E_DIM * G_DIM) / 1024, 256>>>(W);

    dim3 tgrid(S_DIM / 32, B_DIM / 32), tblk(32, 8);
    transpose_kernel<<<tgrid, tblk>>>(x);

    dim3 rgrid(B_DIM / 1024, G_DIM);
    segreduce_kernel<<<rgrid, 256>>>(agg);

    dim3 ggrid(E_DIM / TILE_M, B_DIM / TILE_N);   // 8 x 32 = 256 blocks
    gemm_kernel<<<ggrid, 256>>>(out);
}

// round 13
// speedup vs baseline: 1.0800x; 1.0800x over previous
#include <cuda_runtime.h>
#include <cuda_fp16.h>
#include <cstdint>

#define B_DIM 2048
#define S_DIM 32768
#define G_DIM 4096
#define E_DIM 1024

// ---------------- scratch (static device globals; no allocation) ----------------
__device__ __half    g_xpt[(size_t)S_DIM * B_DIM];  // permuted+transformed transpose (S,B) fp16
__device__ float     g_zt [(size_t)G_DIM * B_DIM];  // relu(finalized y), tf32-rounded, (G,B)
__device__ unsigned  g_wt [(size_t)E_DIM * G_DIM];  // W tf32 bits, k-pair permuted per octet
__device__ int       g_dest[S_DIM];
__device__ float     g_coef[S_DIM];
__device__ int       g_isor[S_DIM];
__device__ int       g_segstart[G_DIM + 1];

__device__ __forceinline__ unsigned cvt_tf32(float f) {
    unsigned r;
    asm("cvt.rna.tf32.f32 %0, %1;" : "=r"(r) : "f"(f));
    return r;
}

// ---------------- prep + wcvt (merged) ----------------
// All 4096 blocks convert W; threads with s<S_DIM also build perm inverse / seg
// bounds. W permutation: within each k-octet, logical j -> 2*(j%4)+(j/4), so the
// GEMM's (k, k+4) fragment pair is adjacent -> LDS.64 in the hot loop.
__global__ void prep_kernel(const float* __restrict__ W,
                            const float* __restrict__ w_elem,
                            const int* __restrict__ perm,
                            const int* __restrict__ seg,
                            const int* __restrict__ agg) {
    size_t i4 = ((size_t)blockIdx.x * 256 + threadIdx.x) * 4;
    float4 v = *(const float4*)&W[i4];
    size_t base = i4 & ~(size_t)7;
    int h = (int)((i4 >> 2) & 1);
    g_wt[base + 0 + h] = cvt_tf32(v.x);
    g_wt[base + 2 + h] = cvt_tf32(v.y);
    g_wt[base + 4 + h] = cvt_tf32(v.z);
    g_wt[base + 6 + h] = cvt_tf32(v.w);

    int s = blockIdx.x * 256 + threadIdx.x;
    if (s < S_DIM) {
        int c = perm[s];
        int g = seg[s];
        int t = agg[g];
        g_dest[c] = s;
        g_coef[c] = (t == 2) ? w_elem[s] : 1.0f;
        g_isor[c] = (t == 1) ? 1 : 0;
        if (s == 0 || seg[s - 1] != g) g_segstart[g] = s;
        if (s == S_DIM - 1) g_segstart[G_DIM] = S_DIM;
    }
}

// ---------------- phase 1: tiled transpose + transform (fp16 out) -------------
// Indicator is computed in fp32 BEFORE the fp16 store (0/1 exact in fp16).
__global__ void transpose_kernel(const float* __restrict__ x) {
    __shared__ float tile[32][33];           // tile[b_local][c_local]
    int c0 = blockIdx.x * 32;
    int b0 = blockIdx.y * 32;
    int tx = threadIdx.x, ty = threadIdx.y;
    #pragma unroll
    for (int j = 0; j < 4; j++) {
        int b = b0 + ty + j * 8;
        tile[ty + j * 8][tx] = x[(size_t)b * S_DIM + c0 + tx];
    }
    __syncthreads();

    int tid = ty * 32 + tx;
    int c_row = tid / 8;                     // 0..31 (local c)
    int th    = tid % 8;                     // 0..7  (b slot, 4 elems)
    int c = c0 + c_row;
    int s = g_dest[c];
    float coef = g_coef[c];
    int isor = g_isor[c];
    float4 v;
    // bank = (th*4 + i + c_row) % 32 -> conflict-free per i
    v.x = tile[th * 4 + 0][c_row];
    v.y = tile[th * 4 + 1][c_row];
    v.z = tile[th * 4 + 2][c_row];
    v.w = tile[th * 4 + 3][c_row];
    if (isor) {
        v.x = v.x != 0.0f ? 1.0f : 0.0f;
        v.y = v.y != 0.0f ? 1.0f : 0.0f;
        v.z = v.z != 0.0f ? 1.0f : 0.0f;
        v.w = v.w != 0.0f ? 1.0f : 0.0f;
    } else {
        v.x *= coef; v.y *= coef; v.z *= coef; v.w *= coef;
    }
    __half2 p0 = __floats2half2_rn(v.x, v.y);
    __half2 p1 = __floats2half2_rn(v.z, v.w);
    uint2 pk;
    pk.x = *(unsigned*)&p0;
    pk.y = *(unsigned*)&p1;
    *(uint2*)&g_xpt[(size_t)s * B_DIM + b0 + th * 4] = pk;
}

// ---------------- phase 2: segmented sum (fp16 in) + finalize + relu ----------
__global__ void segreduce_kernel(const int* __restrict__ agg) {
    int b4 = blockIdx.x * 256 + threadIdx.x;   // 4 b per thread
    int g = blockIdx.y;
    int s0 = g_segstart[g];
    int s1 = g_segstart[g + 1];
    float4 acc = make_float4(0.f, 0.f, 0.f, 0.f);
    for (int s = s0; s < s1; s++) {
        uint2 pk = *(const uint2*)&g_xpt[(size_t)s * B_DIM + b4 * 4];
        float2 f0 = __half22float2(*(__half2*)&pk.x);
        float2 f1 = __half22float2(*(__half2*)&pk.y);
        acc.x += f0.x; acc.y += f0.y; acc.z += f1.x; acc.w += f1.y;
    }
    int t = agg[g];
    if (t == 1) {
        acc.x = acc.x > 0.f ? 1.f : 0.f;
        acc.y = acc.y > 0.f ? 1.f : 0.f;
        acc.z = acc.z > 0.f ? 1.f : 0.f;
        acc.w = acc.w > 0.f ? 1.f : 0.f;
    }
    acc.x = __uint_as_float(cvt_tf32(fmaxf(acc.x, 0.f)));
    acc.y = __uint_as_float(cvt_tf32(fmaxf(acc.y, 0.f)));
    acc.z = __uint_as_float(cvt_tf32(fmaxf(acc.z, 0.f)));
    acc.w = __uint_as_float(cvt_tf32(fmaxf(acc.w, 0.f)));
    *(float4*)&g_zt[(size_t)g * B_DIM + b4 * 4] = acc;
}

// ---------------- phase 3: tf32 mma.sync GEMM, cp.async double-buffered -------
// outT[e][b] = sum_g W[e][g] * zt[g][b];  A = g_wt (k-pair permuted), B = g_zt
// Tile 128(e) x 64(b) x 32(g); 8 warps (warp = 32e x 32b); 2 CTAs/SM; 48KB smem.
#define TILE_M 128
#define TILE_N 64
#define TILE_K 32

__device__ __forceinline__ void cp16(void* smem, const void* gmem) {
    unsigned saddr = (unsigned)__cvta_generic_to_shared(smem);
    asm volatile("cp.async.cg.shared.global [%0], [%1], 16;" :: "r"(saddr), "l"(gmem));
}

__global__ __launch_bounds__(256, 2) void gemm_kernel(float* __restrict__ out) {
    // XOR-swizzled, no padding: exactly 48KB for 2 stages.
    __shared__ unsigned As[2][TILE_M][TILE_K];  // [m=e][kperm], phys c' = c ^ (4*(m%8))
    __shared__ unsigned Bs[2][TILE_K][TILE_N];  // [k][n=b], phys n' = n ^ (8*(k%8))

    int tid = threadIdx.x;
    int warp = tid / 32;
    int lane = tid % 32;
    int e0 = blockIdx.x * TILE_M;
    int b0 = blockIdx.y * TILE_N;
    int wm = (warp % 4) * 32;
    int wn = (warp / 4) * 32;

    // Global->smem load mapping (float4 per cp.async)
    int a_row = tid / 8;                              // +32 per pass, 4 passes
    int a_k4  = tid % 8;
    int b_k   = tid / 16;                             // +16 per pass, 2 passes
    int b_n4  = tid % 16;
    int a_scol = (a_k4 * 4) ^ ((a_row % 8) * 4);      // swizzled store col (A)
    int b_scol = (b_n4 * 4) ^ ((b_k % 8) * 8);        // swizzled store col (B)

    const unsigned* Wp = g_wt;
    const unsigned* Zp = (const unsigned*)g_zt;

    float acc[2][4][4];
    #pragma unroll
    for (int i = 0; i < 2; i++)
        #pragma unroll
        for (int j = 0; j < 4; j++)
            #pragma unroll
            for (int r = 0; r < 4; r++) acc[i][j][r] = 0.f;

    int row = lane / 4;   // 0..7
    int col = lane % 4;   // 0..3

    // Prefetch tile 0 into buffer 0
    #pragma unroll
    for (int p = 0; p < 4; p++)
        cp16(&As[0][a_row + p * 32][a_scol],
             &Wp[(size_t)(e0 + a_row + p * 32) * G_DIM + a_k4 * 4]);
    #pragma unroll
    for (int p = 0; p < 2; p++)
        cp16(&Bs[0][b_k + p * 16][b_scol],
             &Zp[(size_t)(b_k + p * 16) * B_DIM + b0 + b_n4 * 4]);
    asm volatile("cp.async.commit_group;");

    const int T = G_DIM / TILE_K;   // 128
    for (int t = 0; t < T; t++) {
        int cur = t & 1;
        if (t + 1 < T) {
            int nxt = (t + 1) & 1;
            int g0 = (t + 1) * TILE_K;
            #pragma unroll
            for (int p = 0; p < 4; p++)
                cp16(&As[nxt][a_row + p * 32][a_scol],
                     &Wp[(size_t)(e0 + a_row + p * 32) * G_DIM + g0 + a_k4 * 4]);
            #pragma unroll
            for (int p = 0; p < 2; p++)
                cp16(&Bs[nxt][b_k + p * 16][b_scol],
                     &Zp[(size_t)(g0 + b_k + p * 16) * B_DIM + b0 + b_n4 * 4]);
            asm volatile("cp.async.commit_group;");
            asm volatile("cp.async.wait_group 1;");
        } else {
            asm volatile("cp.async.wait_group 0;");
        }
        __syncthreads();

        #pragma unroll
        for (int s = 0; s < 4; s++) {
            // A fragments: permuted layout puts logical (k, k+4) at adjacent
            // columns (8s+2col, 8s+2col+1) -> one LDS.64 per m-row.
            int pc = (8 * s + 2 * col) ^ (4 * row);   // even -> 8B aligned
            unsigned af[2][4], bf[4][2];
            #pragma unroll
            for (int i = 0; i < 2; i++) {
                int m = wm + i * 16 + row;
                uint2 u = *(const uint2*)&As[cur][m    ][pc];
                uint2 w = *(const uint2*)&As[cur][m + 8][pc];
                af[i][0] = u.x; af[i][1] = w.x; af[i][2] = u.y; af[i][3] = w.y;
            }
            int kr0 = s * 8 + col;                    // B k rows
            int swz = 8 * col;
            #pragma unroll
            for (int j = 0; j < 4; j++) {
                int n = wn + j * 8 + row;
                bf[j][0] = Bs[cur][kr0    ][n ^ swz];
                bf[j][1] = Bs[cur][kr0 + 4][n ^ swz ^ 32];
            }
            #pragma unroll
            for (int i = 0; i < 2; i++)
                #pragma unroll
                for (int j = 0; j < 4; j++) {
                    asm volatile(
                        "mma.sync.aligned.m16n8k8.row.col.f32.tf32.tf32.f32 "
                        "{%0,%1,%2,%3}, {%4,%5,%6,%7}, {%8,%9}, {%0,%1,%2,%3};"
                        : "+f"(acc[i][j][0]), "+f"(acc[i][j][1]),
                          "+f"(acc[i][j][2]), "+f"(acc[i][j][3])
                        : "r"(af[i][0]), "r"(af[i][1]), "r"(af[i][2]), "r"(af[i][3]),
                          "r"(bf[j][0]), "r"(bf[j][1]));
                }
        }
        __syncthreads();
    }

    // Epilogue: out[b][e]; c-frag: c0:(m=row,n=2col) c1:(row,2col+1) c2/c3: m=row+8
    #pragma unroll
    for (int i = 0; i < 2; i++) {
        int e_lo = e0 + wm + i * 16 + row;
        #pragma unroll
        for (int j = 0; j < 4; j++) {
            int b_base = b0 + wn + j * 8 + col * 2;
            out[(size_t)(b_base    ) * E_DIM + e_lo    ] = acc[i][j][0];
            out[(size_t)(b_base + 1) * E_DIM + e_lo    ] = acc[i][j][1];
            out[(size_t)(b_base    ) * E_DIM + e_lo + 8] = acc[i][j][2];
            out[(size_t)(b_base + 1) * E_DIM + e_lo + 8] = acc[i][j][3];
        }
    }
}

// ---------------- launch ----------------
extern "C" void kernel_launch(void* const* d_in, const int* in_sizes, int n_in,
                              void* d_out, int out_size) {
    const float* x      = (const float*)d_in[0];
    const float* W      = (const float*)d_in[1];
    const float* w_elem = (const float*)d_in[2];
    const int*   perm   = (const int*)d_in[3];
    const int*   seg    = (const int*)d_in[4];
    const int*   agg    = (const int*)d_in[5];
    float* out = (float*)d_out;

    prep_kernel<<<(E_DIM * G_DIM) / 1024, 256>>>(W, w_elem, perm, seg, agg);

    dim3 tgrid(S_DIM / 32, B_DIM / 32), tblk(32, 8);
    transpose_kernel<<<tgrid, tblk>>>(x);

    dim3 rgrid(B_DIM / 1024, G_DIM);
    segreduce_kernel<<<rgrid, 256>>>(agg);

    dim3 ggrid(E_DIM / TILE_M, B_DIM / TILE_N);   // 8 x 32 = 256 blocks
    gemm_kernel<<<ggrid, 256>>>(out);
}